// round 16
// baseline (speedup 1.0000x reference)
#include <cuda_runtime.h>
#include <cuda_bf16.h>
#include <cuda_fp16.h>
#include <math.h>
#include <cstdint>

#define NMAX 50000
#define EMAX 800000
#define F 256
#define EPS 1e-5f

// ---- device scratch ----
__device__ __half         g_h16[(size_t)NMAX * F];
__device__ __half         g_agg16[(size_t)NMAX * F];   // aggregate result (pre-LN)
__device__ __nv_bfloat16  g_xh[(size_t)NMAX * F];
__device__ __nv_bfloat16  g_xl[(size_t)NMAX * F];
__device__ __nv_bfloat16  g_wth[F * F];       // W^T high  [n][k]
__device__ __nv_bfloat16  g_wtl[F * F];       // W^T low
__device__ float  g_dinv[NMAX];
__device__ int    g_deg[NMAX];
__device__ int    g_fill[NMAX];               // running CSR cursor (init = ptr in scan3)
__device__ int    g_ptr[NMAX + 1];
__device__ int    g_csrc[EMAX];
__device__ int    g_partial[256];             // raw per-block sums from scan1
__device__ double g_stats[2];

// ------------------------------------------------------------------
// block-local edge dtype probe
// ------------------------------------------------------------------
__device__ __forceinline__ int probe_is64(const void* ei, int E) {
    __shared__ int ok_sh;
    if (threadIdx.x == 0) ok_sh = 1;
    __syncthreads();
    int k = (E < 64) ? E : 64;
    if ((int)threadIdx.x < k) {
        long long v = ((const long long*)ei)[threadIdx.x];
        if (v < 0 || v >= NMAX) ok_sh = 0;
    }
    __syncthreads();
    return ok_sh;
}

__device__ __forceinline__ int load_idx(const void* ei, size_t pos, int is64) {
    if (is64) return (int)((const long long*)ei)[pos];
    return ((const int*)ei)[pos];
}

// ------------------------------------------------------------------
// bit-cast helper
// ------------------------------------------------------------------
__device__ __forceinline__ uint32_t h2_bits(__half2 h) {
    uint32_t u;
    *(__half2*)&u = h;
    return u;
}

// ------------------------------------------------------------------
// split helpers
// ------------------------------------------------------------------
__device__ __forceinline__ uint32_t pack_bf16(float a, float b) {
    __nv_bfloat162 t;
    t.x = __float2bfloat16_rn(a);
    t.y = __float2bfloat16_rn(b);
    return *(uint32_t*)&t;
}
__device__ __forceinline__ void split8(const float* f, uint4& h, uint4& l) {
    float hv[8], lv[8];
#pragma unroll
    for (int j = 0; j < 8; j++) {
        __nv_bfloat16 b = __float2bfloat16_rn(f[j]);
        hv[j] = __bfloat162float(b);
        lv[j] = f[j] - hv[j];
    }
    h = make_uint4(pack_bf16(hv[0], hv[1]), pack_bf16(hv[2], hv[3]),
                   pack_bf16(hv[4], hv[5]), pack_bf16(hv[6], hv[7]));
    l = make_uint4(pack_bf16(lv[0], lv[1]), pack_bf16(lv[2], lv[3]),
                   pack_bf16(lv[4], lv[5]), pack_bf16(lv[6], lv[7]));
}

// combined: blocks 0..255 first split+transpose one W column, then all
// 1024 blocks stream X
__global__ void split_xw_kernel(const float* __restrict__ X,
                                const float* __restrict__ W, int n8) {
    if (blockIdx.x < F) {
        int nn = blockIdx.x;
        int k = threadIdx.x;
        float v = W[(size_t)k * F + nn];
        __nv_bfloat16 h = __float2bfloat16_rn(v);
        g_wth[nn * F + k] = h;
        g_wtl[nn * F + k] = __float2bfloat16_rn(v - __bfloat162float(h));
    }
    int i = blockIdx.x * blockDim.x + threadIdx.x;
    for (; i < n8; i += gridDim.x * blockDim.x) {
        float f[8];
        float4 v0 = ((const float4*)X)[i * 2];
        float4 v1 = ((const float4*)X)[i * 2 + 1];
        f[0] = v0.x; f[1] = v0.y; f[2] = v0.z; f[3] = v0.w;
        f[4] = v1.x; f[5] = v1.y; f[6] = v1.z; f[7] = v1.w;
        uint4 h, l;
        split8(f, h, l);
        ((uint4*)g_xh)[i] = h;
        ((uint4*)g_xl)[i] = l;
    }
}

// ------------------------------------------------------------------
// bf16 split GEMM via mma.sync m16n8k16 -> fp16 output only
// ------------------------------------------------------------------
#define PAD 72
#define TILE_BYTES (128 * PAD * 2)
#define AH_OFF 0
#define AL_OFF (TILE_BYTES)
#define BH_OFF (2 * TILE_BYTES)
#define BL_OFF (3 * TILE_BYTES)
#define GSM_TOTAL (4 * TILE_BYTES)

__device__ __forceinline__ void mma_bf16(float* d, const uint32_t* a, const uint32_t* b) {
    asm volatile(
        "mma.sync.aligned.m16n8k16.row.col.f32.bf16.bf16.f32 "
        "{%0,%1,%2,%3}, {%4,%5,%6,%7}, {%8,%9}, {%0,%1,%2,%3};\n"
        : "+f"(d[0]), "+f"(d[1]), "+f"(d[2]), "+f"(d[3])
        : "r"(a[0]), "r"(a[1]), "r"(a[2]), "r"(a[3]), "r"(b[0]), "r"(b[1]));
}

__global__ __launch_bounds__(256) void gemm_mma_kernel(int n) {
    extern __shared__ char smem[];
    int tid = threadIdx.x;
    int wid = tid >> 5;
    int lane = tid & 31;
    int gid = lane >> 2;
    int tig = lane & 3;
    int m0 = blockIdx.y * 128;
    int n0 = blockIdx.x * 128;
    int warpM = (wid >> 2) * 64;
    int warpN = (wid & 3) * 32;

    float acc[4][4][4];
#pragma unroll
    for (int i = 0; i < 4; i++)
#pragma unroll
        for (int j = 0; j < 4; j++)
#pragma unroll
            for (int q = 0; q < 4; q++) acc[i][j][q] = 0.f;

    for (int kc = 0; kc < 4; kc++) {
        int k0 = kc * 64;
        __syncthreads();
#pragma unroll
        for (int it = 0; it < 4; it++) {
            int g = it * 256 + tid;
            int row = g >> 3;
            int c8 = (g & 7) * 8;
            int gm = m0 + row;
            uint4 vh = make_uint4(0, 0, 0, 0), vl = vh;
            if (gm < n) {
                vh = *(const uint4*)&g_xh[(size_t)gm * F + k0 + c8];
                vl = *(const uint4*)&g_xl[(size_t)gm * F + k0 + c8];
            }
            *(uint4*)(smem + AH_OFF + row * (PAD * 2) + c8 * 2) = vh;
            *(uint4*)(smem + AL_OFF + row * (PAD * 2) + c8 * 2) = vl;
        }
#pragma unroll
        for (int it = 0; it < 4; it++) {
            int g = it * 256 + tid;
            int row = g >> 3;
            int c8 = (g & 7) * 8;
            uint4 vh = *(const uint4*)&g_wth[(n0 + row) * F + k0 + c8];
            uint4 vl = *(const uint4*)&g_wtl[(n0 + row) * F + k0 + c8];
            *(uint4*)(smem + BH_OFF + row * (PAD * 2) + c8 * 2) = vh;
            *(uint4*)(smem + BL_OFF + row * (PAD * 2) + c8 * 2) = vl;
        }
        __syncthreads();

#pragma unroll
        for (int ks = 0; ks < 4; ks++) {
            int kb = ks * 16;
            uint32_t ah[4][4], al[4][4], bh[4][2], bl[4][2];
#pragma unroll
            for (int mi = 0; mi < 4; mi++) {
                int r0 = (warpM + mi * 16 + gid) * (PAD * 2);
                int r1 = r0 + 8 * (PAD * 2);
                int cA = (kb + tig * 2) * 2;
                ah[mi][0] = *(const uint32_t*)(smem + AH_OFF + r0 + cA);
                ah[mi][1] = *(const uint32_t*)(smem + AH_OFF + r1 + cA);
                ah[mi][2] = *(const uint32_t*)(smem + AH_OFF + r0 + cA + 16);
                ah[mi][3] = *(const uint32_t*)(smem + AH_OFF + r1 + cA + 16);
                al[mi][0] = *(const uint32_t*)(smem + AL_OFF + r0 + cA);
                al[mi][1] = *(const uint32_t*)(smem + AL_OFF + r1 + cA);
                al[mi][2] = *(const uint32_t*)(smem + AL_OFF + r0 + cA + 16);
                al[mi][3] = *(const uint32_t*)(smem + AL_OFF + r1 + cA + 16);
            }
#pragma unroll
            for (int nj = 0; nj < 4; nj++) {
                int r = (warpN + nj * 8 + gid) * (PAD * 2);
                int cB = (kb + tig * 2) * 2;
                bh[nj][0] = *(const uint32_t*)(smem + BH_OFF + r + cB);
                bh[nj][1] = *(const uint32_t*)(smem + BH_OFF + r + cB + 16);
                bl[nj][0] = *(const uint32_t*)(smem + BL_OFF + r + cB);
                bl[nj][1] = *(const uint32_t*)(smem + BL_OFF + r + cB + 16);
            }
#pragma unroll
            for (int mi = 0; mi < 4; mi++)
#pragma unroll
                for (int nj = 0; nj < 4; nj++) {
                    mma_bf16(acc[mi][nj], ah[mi], bh[nj]);
                    mma_bf16(acc[mi][nj], ah[mi], bl[nj]);
                    mma_bf16(acc[mi][nj], al[mi], bh[nj]);
                }
        }
    }

    // epilogue: fp16 only
#pragma unroll
    for (int mi = 0; mi < 4; mi++) {
        int r0 = m0 + warpM + mi * 16 + gid;
        int r1 = r0 + 8;
#pragma unroll
        for (int nj = 0; nj < 4; nj++) {
            int c = n0 + warpN + nj * 8 + tig * 2;
            if (r0 < n)
                *(__half2*)&g_h16[(size_t)r0 * F + c] =
                    __floats2half2_rn(acc[mi][nj][0], acc[mi][nj][1]);
            if (r1 < n)
                *(__half2*)&g_h16[(size_t)r1 * F + c] =
                    __floats2half2_rn(acc[mi][nj][2], acc[mi][nj][3]);
        }
    }
}

// ------------------------------------------------------------------
// CSR build
// ------------------------------------------------------------------
__global__ void zero_kernel(int n) {
    int i = blockIdx.x * blockDim.x + threadIdx.x;
    for (; i < n; i += gridDim.x * blockDim.x) {
        g_deg[i] = 0;
        if (i < 2) g_stats[i] = 0.0;
    }
}

__global__ void deg_kernel(const void* __restrict__ ei, int E, int n) {
    int is64 = probe_is64(ei, E);
    int e = blockIdx.x * blockDim.x + threadIdx.x;
    for (; e < E; e += gridDim.x * blockDim.x) {
        int d = load_idx(ei, (size_t)E + e, is64);
        if ((unsigned)d < (unsigned)n) atomicAdd(&g_deg[d], 1);
    }
}

// scan1 + fused dinv (coalesced, 512/block); writes RAW block sums
__global__ void scan1_kernel(int n) {
    int i = blockIdx.x * 512 + threadIdx.x;
    int v = (i < n) ? g_deg[i] : 0;
    if (i < n) g_dinv[i] = rsqrtf((float)(v + 1));
    for (int o = 16; o > 0; o >>= 1) v += __shfl_down_sync(~0u, v, o);
    __shared__ int wsum[16];
    int lane = threadIdx.x & 31, wid = threadIdx.x >> 5;
    if (lane == 0) wsum[wid] = v;
    __syncthreads();
    if (wid == 0) {
        int s = (lane < 16) ? wsum[lane] : 0;
        for (int o = 8; o > 0; o >>= 1) s += __shfl_down_sync(~0u, s, o);
        if (lane == 0) g_partial[blockIdx.x] = s;
    }
}

// scan3: each block computes its own offset from raw block sums
// (parallel across blocks — replaces the serial scan2 kernel)
__global__ void scan3_kernel(int n) {
    __shared__ int blk_off;
    int lane = threadIdx.x & 31, wid = threadIdx.x >> 5;
    if (wid == 0) {
        int acc = 0;
        for (int j = lane; j < (int)blockIdx.x; j += 32)
            acc += g_partial[j];
        for (int o = 16; o > 0; o >>= 1) acc += __shfl_down_sync(~0u, acc, o);
        if (lane == 0) blk_off = acc;
    }

    int i = blockIdx.x * 512 + threadIdx.x;
    int v = (i < n) ? g_deg[i] : 0;
    int s = v;
    for (int o = 1; o < 32; o <<= 1) {
        int t = __shfl_up_sync(~0u, s, o);
        if (lane >= o) s += t;
    }
    __shared__ int wsum[16];
    if (lane == 31) wsum[wid] = s;
    __syncthreads();
    if (wid == 0) {
        int ws = (lane < 16) ? wsum[lane] : 0;
        for (int o = 1; o < 16; o <<= 1) {
            int t = __shfl_up_sync(~0u, ws, o);
            if (lane >= o) ws += t;
        }
        if (lane < 16) wsum[lane] = ws;
    }
    __syncthreads();
    int excl = s - v + (wid > 0 ? wsum[wid - 1] : 0) + blk_off;
    if (i < n) {
        g_ptr[i] = excl;
        g_fill[i] = excl;          // cursor starts at ptr (single-atomic fill)
    }
    if (i == n - 1) g_ptr[n] = excl + v;
}

// fill: one atomic per edge (cursor holds absolute position)
__global__ void fill_kernel(const void* __restrict__ ei, int E, int n) {
    int is64 = probe_is64(ei, E);
    int e = blockIdx.x * blockDim.x + threadIdx.x;
    for (; e < E; e += gridDim.x * blockDim.x) {
        int s = load_idx(ei, (size_t)e, is64);
        int d = load_idx(ei, (size_t)E + e, is64);
        if ((unsigned)s >= (unsigned)n || (unsigned)d >= (unsigned)n) continue;
        int pos = atomicAdd(&g_fill[d], 1);
        g_csrc[pos] = s;
    }
}

// ------------------------------------------------------------------
// aggregation: warp per node, fp16 gathers, unroll x8, fp32 accum,
// fp16 output + fused LN stats (stats from fp32 accumulators)
// ------------------------------------------------------------------
__device__ __forceinline__ void acc_row(float* acc, const uint4& p, float nm) {
    const __half2* q = (const __half2*)&p;
#pragma unroll
    for (int j = 0; j < 4; j++) {
        float2 f = __half22float2(q[j]);
        acc[j * 2]     += f.x * nm;
        acc[j * 2 + 1] += f.y * nm;
    }
}

__global__ __launch_bounds__(256) void aggregate_kernel(
    const float* __restrict__ bias, int n) {
    int wrp = threadIdx.x >> 5;
    int lane = threadIdx.x & 31;
    int node = blockIdx.x * 8 + wrp;
    bool valid = (node < n);

    float acc[8];
#pragma unroll
    for (int q = 0; q < 8; q++) acc[q] = 0.f;

    if (valid) {
        float di = g_dinv[node];
        float w = di * di;
        {
            uint4 ps = *(const uint4*)&g_h16[(size_t)node * F + lane * 8];
            acc_row(acc, ps, w);
        }
        int beg = g_ptr[node], end = g_ptr[node + 1];
        int e = beg;
        for (; e + 7 < end; e += 8) {
            int si[8];
            float nm[8];
#pragma unroll
            for (int j = 0; j < 8; j++) si[j] = g_csrc[e + j];
#pragma unroll
            for (int j = 0; j < 8; j++) nm[j] = g_dinv[si[j]] * di;
            uint4 p[8];
#pragma unroll
            for (int j = 0; j < 8; j++)
                p[j] = *(const uint4*)&g_h16[(size_t)si[j] * F + lane * 8];
#pragma unroll
            for (int j = 0; j < 8; j++) acc_row(acc, p[j], nm[j]);
        }
        for (; e + 3 < end; e += 4) {
            int s0 = g_csrc[e],     s1 = g_csrc[e + 1];
            int s2 = g_csrc[e + 2], s3 = g_csrc[e + 3];
            float nm0 = g_dinv[s0] * di, nm1 = g_dinv[s1] * di;
            float nm2 = g_dinv[s2] * di, nm3 = g_dinv[s3] * di;
            uint4 p0 = *(const uint4*)&g_h16[(size_t)s0 * F + lane * 8];
            uint4 p1 = *(const uint4*)&g_h16[(size_t)s1 * F + lane * 8];
            uint4 p2 = *(const uint4*)&g_h16[(size_t)s2 * F + lane * 8];
            uint4 p3 = *(const uint4*)&g_h16[(size_t)s3 * F + lane * 8];
            acc_row(acc, p0, nm0);
            acc_row(acc, p1, nm1);
            acc_row(acc, p2, nm2);
            acc_row(acc, p3, nm3);
        }
        for (; e < end; e++) {
            int s0 = g_csrc[e];
            float nm0 = g_dinv[s0] * di;
            uint4 p0 = *(const uint4*)&g_h16[(size_t)s0 * F + lane * 8];
            acc_row(acc, p0, nm0);
        }
        const float4* bb = (const float4*)&bias[lane * 8];
        float4 b0 = bb[0], b1 = bb[1];
        acc[0] += b0.x; acc[1] += b0.y; acc[2] += b0.z; acc[3] += b0.w;
        acc[4] += b1.x; acc[5] += b1.y; acc[6] += b1.z; acc[7] += b1.w;
        uint4 pk;
        pk.x = h2_bits(__floats2half2_rn(acc[0], acc[1]));
        pk.y = h2_bits(__floats2half2_rn(acc[2], acc[3]));
        pk.z = h2_bits(__floats2half2_rn(acc[4], acc[5]));
        pk.w = h2_bits(__floats2half2_rn(acc[6], acc[7]));
        *(uint4*)&g_agg16[(size_t)node * F + lane * 8] = pk;
    }

    // fused LN statistics (from fp32 accumulators)
    float s = 0.f, s2 = 0.f;
#pragma unroll
    for (int q = 0; q < 8; q++) { s += acc[q]; s2 += acc[q] * acc[q]; }
    for (int o = 16; o > 0; o >>= 1) {
        s  += __shfl_down_sync(~0u, s, o);
        s2 += __shfl_down_sync(~0u, s2, o);
    }
    __shared__ float sh_s[8], sh_s2[8];
    if (lane == 0) { sh_s[wrp] = s; sh_s2[wrp] = s2; }
    __syncthreads();
    if (threadIdx.x == 0) {
        double a = 0.0, b = 0.0;
        for (int i = 0; i < 8; i++) { a += (double)sh_s[i]; b += (double)sh_s2[i]; }
        atomicAdd(&g_stats[0], a);
        atomicAdd(&g_stats[1], b);
    }
}

// ------------------------------------------------------------------
// finalize: layernorm + PReLU; reads fp16 intermediate, writes fp32 out
// ------------------------------------------------------------------
__global__ void finalize_kernel(float* __restrict__ out,
                                const float* __restrict__ lnw,
                                const float* __restrict__ lnb,
                                const float* __restrict__ pa, int M8) {
    long long M = (long long)M8 * 8;
    double mu = g_stats[0] / (double)M;
    double var = g_stats[1] / (double)M - mu * mu;
    if (var < 0.0) var = 0.0;
    float inv = 1.f / ((float)sqrt(var) + EPS);
    float fmu = (float)mu;
    float alpha = pa[0];
    int i = blockIdx.x * blockDim.x + threadIdx.x;
    for (; i < M8; i += gridDim.x * blockDim.x) {
        int c = (i * 8) & (F - 1);
        uint4 p = ((const uint4*)g_agg16)[i];
        const __half2* q = (const __half2*)&p;
        float4 w0 = *(const float4*)&lnw[c];
        float4 w1 = *(const float4*)&lnw[c + 4];
        float4 b0 = *(const float4*)&lnb[c];
        float4 b1 = *(const float4*)&lnb[c + 4];
        float v[8];
#pragma unroll
        for (int j = 0; j < 4; j++) {
            float2 f = __half22float2(q[j]);
            v[j * 2] = f.x; v[j * 2 + 1] = f.y;
        }
        float wv[8] = {w0.x, w0.y, w0.z, w0.w, w1.x, w1.y, w1.z, w1.w};
        float bv[8] = {b0.x, b0.y, b0.z, b0.w, b1.x, b1.y, b1.z, b1.w};
        float4 o0, o1;
#pragma unroll
        for (int j = 0; j < 8; j++) {
            float y = (v[j] - fmu) * inv * wv[j] + bv[j];
            y = (y >= 0.f) ? y : alpha * y;
            if (j < 4) ((float*)&o0)[j] = y; else ((float*)&o1)[j - 4] = y;
        }
        ((float4*)out)[i * 2] = o0;
        ((float4*)out)[i * 2 + 1] = o1;
    }
}

// ------------------------------------------------------------------
extern "C" void kernel_launch(void* const* d_in, const int* in_sizes, int n_in,
                              void* d_out, int out_size) {
    const float* x        = (const float*)d_in[0];
    const void*  ei       = d_in[1];
    const float* W        = (const float*)d_in[3];
    const float* conv_b   = (const float*)d_in[4];
    const float* lnw      = (const float*)d_in[5];
    const float* lnb      = (const float*)d_in[6];
    const float* pa       = (const float*)d_in[7];
    float* out = (float*)d_out;

    int n = in_sizes[0] / F;
    int E = in_sizes[1] / 2;
    int M = n * F;
    int nb = (n + 511) / 512;

    cudaFuncSetAttribute(gemm_mma_kernel,
                         cudaFuncAttributeMaxDynamicSharedMemorySize, GSM_TOTAL);

    // side stream + fork/join events (never destroyed; only 2 non-replayed calls)
    cudaStream_t s1;
    cudaStreamCreateWithFlags(&s1, cudaStreamNonBlocking);
    cudaEvent_t eFork, eJoin;
    cudaEventCreateWithFlags(&eFork, cudaEventDisableTiming);
    cudaEventCreateWithFlags(&eJoin, cudaEventDisableTiming);

    // fork: CSR branch on s1 (scan2 eliminated)
    cudaEventRecord(eFork, 0);
    cudaStreamWaitEvent(s1, eFork, 0);
    zero_kernel<<<128, 512, 0, s1>>>(n);
    deg_kernel<<<1024, 256, 0, s1>>>(ei, E, n);
    scan1_kernel<<<nb, 512, 0, s1>>>(n);
    scan3_kernel<<<nb, 512, 0, s1>>>(n);
    fill_kernel<<<1024, 256, 0, s1>>>(ei, E, n);
    cudaEventRecord(eJoin, s1);

    // GEMM branch on main stream (2 launches)
    split_xw_kernel<<<1024, 256>>>(x, W, M / 8);
    gemm_mma_kernel<<<dim3(2, (n + 127) / 128), 256, GSM_TOTAL>>>(n);

    // join, then aggregate + finalize
    cudaStreamWaitEvent(0, eJoin, 0);
    aggregate_kernel<<<(n + 7) / 8, 256>>>(conv_b, n);
    finalize_kernel<<<512, 256>>>(out, lnw, lnb, pa, M / 8);
}

// round 17
// speedup vs baseline: 1.0582x; 1.0582x over previous
#include <cuda_runtime.h>
#include <cuda_bf16.h>
#include <cuda_fp16.h>
#include <math.h>
#include <cstdint>

#define NMAX 50000
#define EMAX 800000
#define F 256
#define EPS 1e-5f

// ---- device scratch ----
__device__ __half         g_h16[(size_t)NMAX * F];
__device__ __half         g_agg16[(size_t)NMAX * F];   // aggregate result (pre-LN)
__device__ __nv_bfloat16  g_xh[(size_t)NMAX * F];
__device__ __nv_bfloat16  g_xl[(size_t)NMAX * F];
__device__ __nv_bfloat16  g_wth[F * F];       // W^T high  [n][k]
__device__ __nv_bfloat16  g_wtl[F * F];       // W^T low
__device__ float  g_dinv[NMAX];
__device__ int    g_deg[NMAX];
__device__ int    g_fill[NMAX];               // running CSR cursor (init = ptr in scan3)
__device__ int    g_ptr[NMAX + 1];
__device__ int    g_csrc[EMAX];
__device__ int    g_partial[256];             // raw per-block sums from scan1
__device__ double g_stats[2];

// ------------------------------------------------------------------
// block-local edge dtype probe
// ------------------------------------------------------------------
__device__ __forceinline__ int probe_is64(const void* ei, int E) {
    __shared__ int ok_sh;
    if (threadIdx.x == 0) ok_sh = 1;
    __syncthreads();
    int k = (E < 64) ? E : 64;
    if ((int)threadIdx.x < k) {
        long long v = ((const long long*)ei)[threadIdx.x];
        if (v < 0 || v >= NMAX) ok_sh = 0;
    }
    __syncthreads();
    return ok_sh;
}

__device__ __forceinline__ int load_idx(const void* ei, size_t pos, int is64) {
    if (is64) return (int)((const long long*)ei)[pos];
    return ((const int*)ei)[pos];
}

// ------------------------------------------------------------------
// bit-cast helper
// ------------------------------------------------------------------
__device__ __forceinline__ uint32_t h2_bits(__half2 h) {
    uint32_t u;
    *(__half2*)&u = h;
    return u;
}

// ------------------------------------------------------------------
// split helpers
// ------------------------------------------------------------------
__device__ __forceinline__ uint32_t pack_bf16(float a, float b) {
    __nv_bfloat162 t;
    t.x = __float2bfloat16_rn(a);
    t.y = __float2bfloat16_rn(b);
    return *(uint32_t*)&t;
}
__device__ __forceinline__ void split8(const float* f, uint4& h, uint4& l) {
    float hv[8], lv[8];
#pragma unroll
    for (int j = 0; j < 8; j++) {
        __nv_bfloat16 b = __float2bfloat16_rn(f[j]);
        hv[j] = __bfloat162float(b);
        lv[j] = f[j] - hv[j];
    }
    h = make_uint4(pack_bf16(hv[0], hv[1]), pack_bf16(hv[2], hv[3]),
                   pack_bf16(hv[4], hv[5]), pack_bf16(hv[6], hv[7]));
    l = make_uint4(pack_bf16(lv[0], lv[1]), pack_bf16(lv[2], lv[3]),
                   pack_bf16(lv[4], lv[5]), pack_bf16(lv[6], lv[7]));
}

// combined: blocks 0..255 first split+transpose one W column, then all
// 1024 blocks stream X
__global__ void split_xw_kernel(const float* __restrict__ X,
                                const float* __restrict__ W, int n8) {
    if (blockIdx.x < F) {
        int nn = blockIdx.x;
        int k = threadIdx.x;
        float v = W[(size_t)k * F + nn];
        __nv_bfloat16 h = __float2bfloat16_rn(v);
        g_wth[nn * F + k] = h;
        g_wtl[nn * F + k] = __float2bfloat16_rn(v - __bfloat162float(h));
    }
    int i = blockIdx.x * blockDim.x + threadIdx.x;
    for (; i < n8; i += gridDim.x * blockDim.x) {
        float f[8];
        float4 v0 = ((const float4*)X)[i * 2];
        float4 v1 = ((const float4*)X)[i * 2 + 1];
        f[0] = v0.x; f[1] = v0.y; f[2] = v0.z; f[3] = v0.w;
        f[4] = v1.x; f[5] = v1.y; f[6] = v1.z; f[7] = v1.w;
        uint4 h, l;
        split8(f, h, l);
        ((uint4*)g_xh)[i] = h;
        ((uint4*)g_xl)[i] = l;
    }
}

// ------------------------------------------------------------------
// bf16 split GEMM via mma.sync m16n8k16, cp.async double-buffered staging
// ------------------------------------------------------------------
#define PAD 72
#define TILE_BYTES (128 * PAD * 2)            // 18432 per tile (A or B, h or l)
#define AH_OFF 0
#define AL_OFF (TILE_BYTES)
#define BH_OFF (2 * TILE_BYTES)
#define BL_OFF (3 * TILE_BYTES)
#define BUF_BYTES (4 * TILE_BYTES)            // 73728 per buffer
#define GSM_TOTAL (2 * BUF_BYTES)             // 147456

__device__ __forceinline__ void mma_bf16(float* d, const uint32_t* a, const uint32_t* b) {
    asm volatile(
        "mma.sync.aligned.m16n8k16.row.col.f32.bf16.bf16.f32 "
        "{%0,%1,%2,%3}, {%4,%5,%6,%7}, {%8,%9}, {%0,%1,%2,%3};\n"
        : "+f"(d[0]), "+f"(d[1]), "+f"(d[2]), "+f"(d[3])
        : "r"(a[0]), "r"(a[1]), "r"(a[2]), "r"(a[3]), "r"(b[0]), "r"(b[1]));
}

__device__ __forceinline__ void cp16(uint32_t dst_smem, const void* src, int sz) {
    asm volatile("cp.async.cg.shared.global [%0], [%1], 16, %2;\n"
                 :: "r"(dst_smem), "l"(src), "r"(sz));
}

__global__ __launch_bounds__(256) void gemm_mma_kernel(int n) {
    extern __shared__ char smem[];
    uint32_t smem_u32;
    asm("{ .reg .u64 t; cvta.to.shared.u64 t, %1; cvt.u32.u64 %0, t; }"
        : "=r"(smem_u32) : "l"(smem));
    int tid = threadIdx.x;
    int wid = tid >> 5;
    int lane = tid & 31;
    int gid = lane >> 2;
    int tig = lane & 3;
    int m0 = blockIdx.y * 128;
    int n0 = blockIdx.x * 128;
    int warpM = (wid >> 2) * 64;
    int warpN = (wid & 3) * 32;

    // per-thread staging coordinates: 4 iterations, row = idx>>3, chunk = idx&7
    // each thread copies 4 x (AH,AL) rows-chunks and 4 x (BH,BL)

    float acc[4][4][4];
#pragma unroll
    for (int i = 0; i < 4; i++)
#pragma unroll
        for (int j = 0; j < 4; j++)
#pragma unroll
            for (int q = 0; q < 4; q++) acc[i][j][q] = 0.f;

    // ---- async stage of chunk kc into buffer buf ----
    auto stage = [&](int buf, int kc) {
        int k0 = kc * 64;
        uint32_t base = smem_u32 + buf * BUF_BYTES;
#pragma unroll
        for (int it = 0; it < 4; it++) {
            int g = it * 256 + tid;
            int row = g >> 3;
            int c8 = (g & 7) * 8;
            uint32_t off = row * (PAD * 2) + c8 * 2;
            int gm = m0 + row;
            int sz = (gm < n) ? 16 : 0;
            size_t gofs = (size_t)(gm < n ? gm : 0) * F + k0 + c8;
            cp16(base + AH_OFF + off, &g_xh[gofs], sz);
            cp16(base + AL_OFF + off, &g_xl[gofs], sz);
            cp16(base + BH_OFF + off, &g_wth[(n0 + row) * F + k0 + c8], 16);
            cp16(base + BL_OFF + off, &g_wtl[(n0 + row) * F + k0 + c8], 16);
        }
        asm volatile("cp.async.commit_group;\n");
    };

    stage(0, 0);

#pragma unroll 1
    for (int kc = 0; kc < 4; kc++) {
        int buf = kc & 1;
        if (kc + 1 < 4) stage(buf ^ 1, kc + 1);
        if (kc + 1 < 4) asm volatile("cp.async.wait_group 1;\n");
        else            asm volatile("cp.async.wait_group 0;\n");
        __syncthreads();

        const char* bp = smem + buf * BUF_BYTES;
#pragma unroll
        for (int ks = 0; ks < 4; ks++) {
            int kb = ks * 16;
            uint32_t ah[4][4], al[4][4], bh[4][2], bl[4][2];
#pragma unroll
            for (int mi = 0; mi < 4; mi++) {
                int r0 = (warpM + mi * 16 + gid) * (PAD * 2);
                int r1 = r0 + 8 * (PAD * 2);
                int cA = (kb + tig * 2) * 2;
                ah[mi][0] = *(const uint32_t*)(bp + AH_OFF + r0 + cA);
                ah[mi][1] = *(const uint32_t*)(bp + AH_OFF + r1 + cA);
                ah[mi][2] = *(const uint32_t*)(bp + AH_OFF + r0 + cA + 16);
                ah[mi][3] = *(const uint32_t*)(bp + AH_OFF + r1 + cA + 16);
                al[mi][0] = *(const uint32_t*)(bp + AL_OFF + r0 + cA);
                al[mi][1] = *(const uint32_t*)(bp + AL_OFF + r1 + cA);
                al[mi][2] = *(const uint32_t*)(bp + AL_OFF + r0 + cA + 16);
                al[mi][3] = *(const uint32_t*)(bp + AL_OFF + r1 + cA + 16);
            }
#pragma unroll
            for (int nj = 0; nj < 4; nj++) {
                int r = (warpN + nj * 8 + gid) * (PAD * 2);
                int cB = (kb + tig * 2) * 2;
                bh[nj][0] = *(const uint32_t*)(bp + BH_OFF + r + cB);
                bh[nj][1] = *(const uint32_t*)(bp + BH_OFF + r + cB + 16);
                bl[nj][0] = *(const uint32_t*)(bp + BL_OFF + r + cB);
                bl[nj][1] = *(const uint32_t*)(bp + BL_OFF + r + cB + 16);
            }
#pragma unroll
            for (int mi = 0; mi < 4; mi++)
#pragma unroll
                for (int nj = 0; nj < 4; nj++) {
                    mma_bf16(acc[mi][nj], ah[mi], bh[nj]);
                    mma_bf16(acc[mi][nj], ah[mi], bl[nj]);
                    mma_bf16(acc[mi][nj], al[mi], bh[nj]);
                }
        }
        __syncthreads();   // buffer reuse safety before next stage into it
    }

    // epilogue: fp16 only
#pragma unroll
    for (int mi = 0; mi < 4; mi++) {
        int r0 = m0 + warpM + mi * 16 + gid;
        int r1 = r0 + 8;
#pragma unroll
        for (int nj = 0; nj < 4; nj++) {
            int c = n0 + warpN + nj * 8 + tig * 2;
            if (r0 < n)
                *(__half2*)&g_h16[(size_t)r0 * F + c] =
                    __floats2half2_rn(acc[mi][nj][0], acc[mi][nj][1]);
            if (r1 < n)
                *(__half2*)&g_h16[(size_t)r1 * F + c] =
                    __floats2half2_rn(acc[mi][nj][2], acc[mi][nj][3]);
        }
    }
}

// ------------------------------------------------------------------
// CSR build
// ------------------------------------------------------------------
__global__ void zero_kernel(int n) {
    int i = blockIdx.x * blockDim.x + threadIdx.x;
    for (; i < n; i += gridDim.x * blockDim.x) {
        g_deg[i] = 0;
        if (i < 2) g_stats[i] = 0.0;
    }
}

__global__ void deg_kernel(const void* __restrict__ ei, int E, int n) {
    int is64 = probe_is64(ei, E);
    int e = blockIdx.x * blockDim.x + threadIdx.x;
    for (; e < E; e += gridDim.x * blockDim.x) {
        int d = load_idx(ei, (size_t)E + e, is64);
        if ((unsigned)d < (unsigned)n) atomicAdd(&g_deg[d], 1);
    }
}

// scan1 + fused dinv (coalesced, 512/block); writes RAW block sums
__global__ void scan1_kernel(int n) {
    int i = blockIdx.x * 512 + threadIdx.x;
    int v = (i < n) ? g_deg[i] : 0;
    if (i < n) g_dinv[i] = rsqrtf((float)(v + 1));
    for (int o = 16; o > 0; o >>= 1) v += __shfl_down_sync(~0u, v, o);
    __shared__ int wsum[16];
    int lane = threadIdx.x & 31, wid = threadIdx.x >> 5;
    if (lane == 0) wsum[wid] = v;
    __syncthreads();
    if (wid == 0) {
        int s = (lane < 16) ? wsum[lane] : 0;
        for (int o = 8; o > 0; o >>= 1) s += __shfl_down_sync(~0u, s, o);
        if (lane == 0) g_partial[blockIdx.x] = s;
    }
}

// scan3: each block computes its own offset from raw block sums
__global__ void scan3_kernel(int n) {
    __shared__ int blk_off;
    int lane = threadIdx.x & 31, wid = threadIdx.x >> 5;
    if (wid == 0) {
        int acc = 0;
        for (int j = lane; j < (int)blockIdx.x; j += 32)
            acc += g_partial[j];
        for (int o = 16; o > 0; o >>= 1) acc += __shfl_down_sync(~0u, acc, o);
        if (lane == 0) blk_off = acc;
    }

    int i = blockIdx.x * 512 + threadIdx.x;
    int v = (i < n) ? g_deg[i] : 0;
    int s = v;
    for (int o = 1; o < 32; o <<= 1) {
        int t = __shfl_up_sync(~0u, s, o);
        if (lane >= o) s += t;
    }
    __shared__ int wsum[16];
    if (lane == 31) wsum[wid] = s;
    __syncthreads();
    if (wid == 0) {
        int ws = (lane < 16) ? wsum[lane] : 0;
        for (int o = 1; o < 16; o <<= 1) {
            int t = __shfl_up_sync(~0u, ws, o);
            if (lane >= o) ws += t;
        }
        if (lane < 16) wsum[lane] = ws;
    }
    __syncthreads();
    int excl = s - v + (wid > 0 ? wsum[wid - 1] : 0) + blk_off;
    if (i < n) {
        g_ptr[i] = excl;
        g_fill[i] = excl;
    }
    if (i == n - 1) g_ptr[n] = excl + v;
}

// fill: one atomic per edge
__global__ void fill_kernel(const void* __restrict__ ei, int E, int n) {
    int is64 = probe_is64(ei, E);
    int e = blockIdx.x * blockDim.x + threadIdx.x;
    for (; e < E; e += gridDim.x * blockDim.x) {
        int s = load_idx(ei, (size_t)e, is64);
        int d = load_idx(ei, (size_t)E + e, is64);
        if ((unsigned)s >= (unsigned)n || (unsigned)d >= (unsigned)n) continue;
        int pos = atomicAdd(&g_fill[d], 1);
        g_csrc[pos] = s;
    }
}

// ------------------------------------------------------------------
// aggregation: warp per node, fp16 gathers, unroll x8, fp32 accum,
// fp16 output + fused LN stats
// ------------------------------------------------------------------
__device__ __forceinline__ void acc_row(float* acc, const uint4& p, float nm) {
    const __half2* q = (const __half2*)&p;
#pragma unroll
    for (int j = 0; j < 4; j++) {
        float2 f = __half22float2(q[j]);
        acc[j * 2]     += f.x * nm;
        acc[j * 2 + 1] += f.y * nm;
    }
}

__global__ __launch_bounds__(256) void aggregate_kernel(
    const float* __restrict__ bias, int n) {
    int wrp = threadIdx.x >> 5;
    int lane = threadIdx.x & 31;
    int node = blockIdx.x * 8 + wrp;
    bool valid = (node < n);

    float acc[8];
#pragma unroll
    for (int q = 0; q < 8; q++) acc[q] = 0.f;

    if (valid) {
        float di = g_dinv[node];
        float w = di * di;
        {
            uint4 ps = *(const uint4*)&g_h16[(size_t)node * F + lane * 8];
            acc_row(acc, ps, w);
        }
        int beg = g_ptr[node], end = g_ptr[node + 1];
        int e = beg;
        for (; e + 7 < end; e += 8) {
            int si[8];
            float nm[8];
#pragma unroll
            for (int j = 0; j < 8; j++) si[j] = g_csrc[e + j];
#pragma unroll
            for (int j = 0; j < 8; j++) nm[j] = g_dinv[si[j]] * di;
            uint4 p[8];
#pragma unroll
            for (int j = 0; j < 8; j++)
                p[j] = *(const uint4*)&g_h16[(size_t)si[j] * F + lane * 8];
#pragma unroll
            for (int j = 0; j < 8; j++) acc_row(acc, p[j], nm[j]);
        }
        for (; e + 3 < end; e += 4) {
            int s0 = g_csrc[e],     s1 = g_csrc[e + 1];
            int s2 = g_csrc[e + 2], s3 = g_csrc[e + 3];
            float nm0 = g_dinv[s0] * di, nm1 = g_dinv[s1] * di;
            float nm2 = g_dinv[s2] * di, nm3 = g_dinv[s3] * di;
            uint4 p0 = *(const uint4*)&g_h16[(size_t)s0 * F + lane * 8];
            uint4 p1 = *(const uint4*)&g_h16[(size_t)s1 * F + lane * 8];
            uint4 p2 = *(const uint4*)&g_h16[(size_t)s2 * F + lane * 8];
            uint4 p3 = *(const uint4*)&g_h16[(size_t)s3 * F + lane * 8];
            acc_row(acc, p0, nm0);
            acc_row(acc, p1, nm1);
            acc_row(acc, p2, nm2);
            acc_row(acc, p3, nm3);
        }
        for (; e < end; e++) {
            int s0 = g_csrc[e];
            float nm0 = g_dinv[s0] * di;
            uint4 p0 = *(const uint4*)&g_h16[(size_t)s0 * F + lane * 8];
            acc_row(acc, p0, nm0);
        }
        const float4* bb = (const float4*)&bias[lane * 8];
        float4 b0 = bb[0], b1 = bb[1];
        acc[0] += b0.x; acc[1] += b0.y; acc[2] += b0.z; acc[3] += b0.w;
        acc[4] += b1.x; acc[5] += b1.y; acc[6] += b1.z; acc[7] += b1.w;
        uint4 pk;
        pk.x = h2_bits(__floats2half2_rn(acc[0], acc[1]));
        pk.y = h2_bits(__floats2half2_rn(acc[2], acc[3]));
        pk.z = h2_bits(__floats2half2_rn(acc[4], acc[5]));
        pk.w = h2_bits(__floats2half2_rn(acc[6], acc[7]));
        *(uint4*)&g_agg16[(size_t)node * F + lane * 8] = pk;
    }

    float s = 0.f, s2 = 0.f;
#pragma unroll
    for (int q = 0; q < 8; q++) { s += acc[q]; s2 += acc[q] * acc[q]; }
    for (int o = 16; o > 0; o >>= 1) {
        s  += __shfl_down_sync(~0u, s, o);
        s2 += __shfl_down_sync(~0u, s2, o);
    }
    __shared__ float sh_s[8], sh_s2[8];
    if (lane == 0) { sh_s[wrp] = s; sh_s2[wrp] = s2; }
    __syncthreads();
    if (threadIdx.x == 0) {
        double a = 0.0, b = 0.0;
        for (int i = 0; i < 8; i++) { a += (double)sh_s[i]; b += (double)sh_s2[i]; }
        atomicAdd(&g_stats[0], a);
        atomicAdd(&g_stats[1], b);
    }
}

// ------------------------------------------------------------------
// finalize: layernorm + PReLU; reads fp16 intermediate, writes fp32 out
// ------------------------------------------------------------------
__global__ void finalize_kernel(float* __restrict__ out,
                                const float* __restrict__ lnw,
                                const float* __restrict__ lnb,
                                const float* __restrict__ pa, int M8) {
    long long M = (long long)M8 * 8;
    double mu = g_stats[0] / (double)M;
    double var = g_stats[1] / (double)M - mu * mu;
    if (var < 0.0) var = 0.0;
    float inv = 1.f / ((float)sqrt(var) + EPS);
    float fmu = (float)mu;
    float alpha = pa[0];
    int i = blockIdx.x * blockDim.x + threadIdx.x;
    for (; i < M8; i += gridDim.x * blockDim.x) {
        int c = (i * 8) & (F - 1);
        uint4 p = ((const uint4*)g_agg16)[i];
        const __half2* q = (const __half2*)&p;
        float4 w0 = *(const float4*)&lnw[c];
        float4 w1 = *(const float4*)&lnw[c + 4];
        float4 b0 = *(const float4*)&lnb[c];
        float4 b1 = *(const float4*)&lnb[c + 4];
        float v[8];
#pragma unroll
        for (int j = 0; j < 4; j++) {
            float2 f = __half22float2(q[j]);
            v[j * 2] = f.x; v[j * 2 + 1] = f.y;
        }
        float wv[8] = {w0.x, w0.y, w0.z, w0.w, w1.x, w1.y, w1.z, w1.w};
        float bv[8] = {b0.x, b0.y, b0.z, b0.w, b1.x, b1.y, b1.z, b1.w};
        float4 o0, o1;
#pragma unroll
        for (int j = 0; j < 8; j++) {
            float y = (v[j] - fmu) * inv * wv[j] + bv[j];
            y = (y >= 0.f) ? y : alpha * y;
            if (j < 4) ((float*)&o0)[j] = y; else ((float*)&o1)[j - 4] = y;
        }
        ((float4*)out)[i * 2] = o0;
        ((float4*)out)[i * 2 + 1] = o1;
    }
}

// ------------------------------------------------------------------
extern "C" void kernel_launch(void* const* d_in, const int* in_sizes, int n_in,
                              void* d_out, int out_size) {
    const float* x        = (const float*)d_in[0];
    const void*  ei       = d_in[1];
    const float* W        = (const float*)d_in[3];
    const float* conv_b   = (const float*)d_in[4];
    const float* lnw      = (const float*)d_in[5];
    const float* lnb      = (const float*)d_in[6];
    const float* pa       = (const float*)d_in[7];
    float* out = (float*)d_out;

    int n = in_sizes[0] / F;
    int E = in_sizes[1] / 2;
    int M = n * F;
    int nb = (n + 511) / 512;

    cudaFuncSetAttribute(gemm_mma_kernel,
                         cudaFuncAttributeMaxDynamicSharedMemorySize, GSM_TOTAL);

    // side stream + fork/join events (never destroyed; only 2 non-replayed calls)
    cudaStream_t s1;
    cudaStreamCreateWithFlags(&s1, cudaStreamNonBlocking);
    cudaEvent_t eFork, eJoin;
    cudaEventCreateWithFlags(&eFork, cudaEventDisableTiming);
    cudaEventCreateWithFlags(&eJoin, cudaEventDisableTiming);

    cudaEventRecord(eFork, 0);
    cudaStreamWaitEvent(s1, eFork, 0);

    // submission order chosen so gemm is the 6th launch (ncu -s 5 -c 1)
    split_xw_kernel<<<1024, 256>>>(x, W, M / 8);            // 1 (main)
    zero_kernel<<<128, 512, 0, s1>>>(n);                    // 2 (s1)
    deg_kernel<<<1024, 256, 0, s1>>>(ei, E, n);             // 3
    scan1_kernel<<<nb, 512, 0, s1>>>(n);                    // 4
    scan3_kernel<<<nb, 512, 0, s1>>>(n);                    // 5
    gemm_mma_kernel<<<dim3(2, (n + 127) / 128), 256, GSM_TOTAL>>>(n);  // 6 (main)
    fill_kernel<<<1024, 256, 0, s1>>>(ei, E, n);            // 7 (s1)
    cudaEventRecord(eJoin, s1);

    cudaStreamWaitEvent(0, eJoin, 0);
    aggregate_kernel<<<(n + 7) / 8, 256>>>(conv_b, n);      // 8
    finalize_kernel<<<512, 256>>>(out, lnw, lnb, pa, M / 8);// 9
}